// round 2
// baseline (speedup 1.0000x reference)
#include <cuda_runtime.h>
#include <math.h>

#define Bb    4
#define Nn    512
#define Dd    48
#define H1    96
#define BN    (Bb * Nn)          // 2048
#define PSTR  49                 // padded pair_out stride (bank-conflict-free)
#define TPB   256

// Static device scratch (no runtime allocation allowed)
__device__ float g_A[BN * H1];    // A[bn][k] = x[bn] @ W1[0:48,:] + b1   (786 KB)
__device__ float g_Ct[H1 * BN];   // Ct[k][bn] = (x[bn] @ W1[48:96,:])^T (786 KB, L2-resident)

__device__ __forceinline__ float gelu_exact(float v) {
    // exact gelu: 0.5 * v * (1 + erf(v / sqrt(2)))
    return 0.5f * v * (1.0f + erff(v * 0.70710678118654752f));
}

// ---------------------------------------------------------------------------
// Kernel 1: per-token halves of the first linear layer.
// grid = BN blocks, 96 threads (one per output channel k).
// ---------------------------------------------------------------------------
__global__ void prep_kernel(const float* __restrict__ x,
                            const float* __restrict__ W1,
                            const float* __restrict__ b1) {
    int bn = blockIdx.x;
    int k  = threadIdx.x;           // 0..95
    __shared__ float sx[Dd];
    if (k < Dd) sx[k] = x[bn * Dd + k];
    __syncthreads();

    float a = b1[k];
    float c = 0.0f;
#pragma unroll
    for (int d = 0; d < Dd; d++) {
        float xv = sx[d];
        a += xv * W1[d * H1 + k];          // coalesced over k
        c += xv * W1[(Dd + d) * H1 + k];
    }
    g_A[bn * H1 + k]  = a;
    g_Ct[k * BN + bn] = c;
}

// ---------------------------------------------------------------------------
// Kernel 2: one CTA per (b, i). Thread-per-j over j in [0, i].
// smem: pair_out[512][49] | w[512] | W2[96*48] | W3[48*48] | A[96] | b2 | b3 | red
// ---------------------------------------------------------------------------
__global__ __launch_bounds__(TPB, 1)
void pair_kernel(const float* __restrict__ W2g, const float* __restrict__ b2g,
                 const float* __restrict__ W3g, const float* __restrict__ b3g,
                 float* __restrict__ out) {
    extern __shared__ float smem[];
    float* sPO  = smem;                    // Nn * PSTR
    float* sw   = sPO + Nn * PSTR;         // Nn
    float* sW2  = sw + Nn;                 // H1 * Dd
    float* sW3  = sW2 + H1 * Dd;           // Dd * Dd
    float* sA   = sW3 + Dd * Dd;           // H1
    float* sB2  = sA + H1;                 // Dd
    float* sB3  = sB2 + Dd;                // Dd
    float* sRed = sB3 + Dd;                // 16

    const int bi  = blockIdx.x;            // 0..BN-1
    const int b   = bi / Nn;
    const int i   = bi % Nn;
    const int tid = threadIdx.x;

    for (int t = tid; t < H1 * Dd; t += TPB) sW2[t] = W2g[t];
    for (int t = tid; t < Dd * Dd; t += TPB) sW3[t] = W3g[t];
    if (tid < H1) sA[tid] = g_A[bi * H1 + tid];
    if (tid < Dd) { sB2[tid] = b2g[tid]; sB3[tid] = b3g[tid]; }
    __syncthreads();

    const int cnt = i + 1;                 // j in [0, i]

    for (int j = tid; j < cnt; j += TPB) {
        // ---- layer 2: h2 = gelu(pair@W1+b1) @ W2 + b2, fused h1 ----
        float h2[Dd];
#pragma unroll
        for (int m = 0; m < Dd; m++) h2[m] = sB2[m];

        const float* ct = &g_Ct[b * Nn + j];   // column j of Ct, stride BN over k
#pragma unroll 1
        for (int k = 0; k < H1; k++) {
            float h1 = gelu_exact(sA[k] + ct[k * BN]);   // coalesced across j-threads
#pragma unroll
            for (int m = 0; m < Dd; m++) h2[m] += h1 * sW2[k * Dd + m];
        }

        // ---- layer 3: out = gelu(h2) @ W3 + b3 ----
        float o[Dd];
#pragma unroll
        for (int d = 0; d < Dd; d++) o[d] = sB3[d];
#pragma unroll 1
        for (int m = 0; m < Dd; m++) {
            float hm = gelu_exact(h2[m]);
#pragma unroll
            for (int d = 0; d < Dd; d++) o[d] += hm * sW3[m * Dd + d];
        }

        // ---- norm + stash row ----
        float nrm = 0.0f;
#pragma unroll
        for (int d = 0; d < Dd; d++) {
            nrm += o[d] * o[d];
            sPO[j * PSTR + d] = o[d];
        }
        sw[j] = sqrtf(nrm);
    }
    __syncthreads();

    // ---- softmax over sw[0..cnt) (masked j>i contribute exactly 0) ----
    // block max
    float v = -1e30f;
    for (int j = tid; j < cnt; j += TPB) v = fmaxf(v, sw[j]);
#pragma unroll
    for (int off = 16; off; off >>= 1) v = fmaxf(v, __shfl_xor_sync(0xFFFFFFFFu, v, off));
    if ((tid & 31) == 0) sRed[tid >> 5] = v;
    __syncthreads();
    if (tid == 0) {
        float m = sRed[0];
#pragma unroll
        for (int w = 1; w < TPB / 32; w++) m = fmaxf(m, sRed[w]);
        sRed[8] = m;
    }
    __syncthreads();
    const float mx = sRed[8];

    // exp + block sum
    float ps = 0.0f;
    for (int j = tid; j < cnt; j += TPB) {
        float e = __expf(sw[j] - mx);
        sw[j] = e;
        ps += e;
    }
#pragma unroll
    for (int off = 16; off; off >>= 1) ps += __shfl_xor_sync(0xFFFFFFFFu, ps, off);
    if ((tid & 31) == 0) sRed[tid >> 5] = ps;
    __syncthreads();
    if (tid == 0) {
        float s = 0.0f;
#pragma unroll
        for (int w = 0; w < TPB / 32; w++) s += sRed[w];
        sRed[9] = 1.0f / s;
    }
    __syncthreads();
    const float inv = sRed[9];

    // ---- weighted sum: out[b,i,d] = sum_j softmax_j * pair_out[j][d] ----
    if (tid < Dd) {
        const int d = tid;
        float acc = 0.0f;
        for (int j = 0; j < cnt; j++)
            acc += sw[j] * sPO[j * PSTR + d];
        out[bi * Dd + d] = acc * inv;
    }
}

// ---------------------------------------------------------------------------
extern "C" void kernel_launch(void* const* d_in, const int* in_sizes, int n_in,
                              void* d_out, int out_size) {
    const float* x  = (const float*)d_in[0];
    const float* W1 = (const float*)d_in[1];
    const float* b1 = (const float*)d_in[2];
    const float* W2 = (const float*)d_in[3];
    const float* b2 = (const float*)d_in[4];
    const float* W3 = (const float*)d_in[5];
    const float* b3 = (const float*)d_in[6];
    float* out = (float*)d_out;

    const int smem_bytes = (Nn * PSTR + Nn + H1 * Dd + Dd * Dd + H1 + Dd + Dd + 16) * sizeof(float);
    static bool attr_set = false;
    cudaFuncSetAttribute(pair_kernel, cudaFuncAttributeMaxDynamicSharedMemorySize, smem_bytes);

    prep_kernel<<<BN, H1>>>(x, W1, b1);
    pair_kernel<<<BN, TPB, smem_bytes>>>(W2, b2, W3, b3, out);
    (void)attr_set; (void)in_sizes; (void)n_in; (void)out_size;
}

// round 4
// speedup vs baseline: 2.3788x; 2.3788x over previous
#include <cuda_runtime.h>
#include <math.h>

#define Bb   4
#define Nn   512
#define Dd   48
#define H1   96
#define BN   (Bb * Nn)
#define TPB  128
#define NW   (TPB / 32)
#define NP   (TPB / 2)      // lane-pairs per CTA = j's per half-tile

typedef unsigned long long u64;

__device__ __align__(16) float g_A[BN * H1];   // A[bn][k] = x@W1_top + b1
__device__ __align__(16) float g_C[BN * H1];   // C[bn][k] = x@W1_bot  (row-major)

__device__ __forceinline__ float gelu_exact(float v) {
    return 0.5f * v * (1.0f + erff(v * 0.70710678118654752f));
}
__device__ __forceinline__ u64 pk(float lo, float hi) {
    u64 r; asm("mov.b64 %0, {%1,%2};" : "=l"(r) : "f"(lo), "f"(hi)); return r;
}
__device__ __forceinline__ u64 pk1(float v) { return pk(v, v); }
__device__ __forceinline__ void upk(u64 v, float& lo, float& hi) {
    asm("mov.b64 {%0,%1}, %2;" : "=f"(lo), "=f"(hi) : "l"(v));
}
__device__ __forceinline__ u64 ffma2(u64 a, u64 b, u64 c) {
    u64 d; asm("fma.rn.f32x2 %0, %1, %2, %3;" : "=l"(d) : "l"(a), "l"(b), "l"(c)); return d;
}
__device__ __forceinline__ u64 fmul2(u64 a, u64 b) {
    u64 d; asm("mul.rn.f32x2 %0, %1, %2;" : "=l"(d) : "l"(a), "l"(b)); return d;
}
__device__ __forceinline__ u64 fadd2(u64 a, u64 b) {
    u64 d; asm("add.rn.f32x2 %0, %1, %2;" : "=l"(d) : "l"(a), "l"(b)); return d;
}

// ---------------------------------------------------------------------------
// Kernel 1: per-token halves of the first linear layer (tiny).
// ---------------------------------------------------------------------------
__global__ void prep_kernel(const float* __restrict__ x,
                            const float* __restrict__ W1,
                            const float* __restrict__ b1) {
    int bn = blockIdx.x;
    int k  = threadIdx.x;            // 0..95
    __shared__ float sx[Dd];
    if (k < Dd) sx[k] = x[bn * Dd + k];
    __syncthreads();
    float a = b1[k], c = 0.0f;
#pragma unroll
    for (int d = 0; d < Dd; d++) {
        float xv = sx[d];
        a += xv * W1[d * H1 + k];
        c += xv * W1[(Dd + d) * H1 + k];
    }
    g_A[bn * H1 + k] = a;
    g_C[bn * H1 + k] = c;
}

// ---------------------------------------------------------------------------
// Kernel 2: one CTA per (b,i). Lane pairs: even lane owns d in [0,24),
// odd lane d in [24,48). Each lane carries TWO j columns (jown, joth).
// Packed f32x2 FMAs throughout; online softmax in registers.
// Denominator: each j contributes ONLY via the lane whose jown it is.
// ---------------------------------------------------------------------------
__global__ __launch_bounds__(TPB, 1)
void pair_kernel(const float* __restrict__ W2g, const float* __restrict__ b2g,
                 const float* __restrict__ W3g, const float* __restrict__ b3g,
                 float* __restrict__ out) {
    __shared__ __align__(16) float sW2[H1 * Dd];
    __shared__ __align__(16) float sW3[Dd * Dd];
    __shared__ __align__(16) float sA[H1];
    __shared__ __align__(16) float sB2[Dd];
    __shared__ __align__(16) float sB3[Dd];
    __shared__ float sRed[16];
    __shared__ float sAcc[NW * Dd];

    const int bi = blockIdx.x, b = bi / Nn, i = bi % Nn;
    const int tid = threadIdx.x, lane = tid & 31, wid = tid >> 5;
    const int half = tid & 1, p = tid >> 1;
    const int dbase = half * 24;
    const int obase = 24 - dbase;

    for (int t = tid; t < H1 * Dd; t += TPB) sW2[t] = W2g[t];
    for (int t = tid; t < Dd * Dd; t += TPB) sW3[t] = W3g[t];
    if (tid < H1) sA[tid] = g_A[bi * H1 + tid];
    if (tid < Dd) { sB2[tid] = b2g[tid]; sB3[tid] = b3g[tid]; }
    __syncthreads();

    float mloc = -1e30f, sloc = 0.0f;
    u64 accp[12];
#pragma unroll
    for (int q = 0; q < 12; q++) accp[q] = pk(0.0f, 0.0f);

    for (int jb = 0; jb <= i; jb += 2 * NP) {
        const int j0 = jb + p;
        const int j1 = jb + NP + p;
        const int jown = half ? j1 : j0;
        const int joth = half ? j0 : j1;
        const int jrow = (jown < Nn) ? jown : (Nn - 1);   // clamp masked tail (no OOB)

        // ---- layer 2: h2 = gelu(A_i + C_j) @ W2 + b2 (d-half, 2 j's) ----
        u64 h2o[12], h2t[12];
#pragma unroll
        for (int q = 0; q < 12; q++) {
            u64 bb = *(const u64*)(sB2 + dbase + 2 * q);
            h2o[q] = bb; h2t[q] = bb;
        }

        const float4* __restrict__ c4 = (const float4*)&g_C[(b * Nn + jrow) * H1];
        float4 cv = c4[0];
#pragma unroll 1
        for (int kk = 0; kk < H1 / 4; kk++) {
            float4 cvn = c4[(kk + 1 < H1 / 4) ? (kk + 1) : kk];   // prefetch
            float4 av = *(const float4*)(sA + 4 * kk);
            float g0 = gelu_exact(av.x + cv.x);
            float g1 = gelu_exact(av.y + cv.y);
            float g2 = gelu_exact(av.z + cv.z);
            float g3 = gelu_exact(av.w + cv.w);
            float t0 = __shfl_xor_sync(0xFFFFFFFFu, g0, 1);
            float t1 = __shfl_xor_sync(0xFFFFFFFFu, g1, 1);
            float t2 = __shfl_xor_sync(0xFFFFFFFFu, g2, 1);
            float t3 = __shfl_xor_sync(0xFFFFFFFFu, g3, 1);
            u64 go0 = pk1(g0), go1 = pk1(g1), go2 = pk1(g2), go3 = pk1(g3);
            u64 gt0 = pk1(t0), gt1 = pk1(t1), gt2 = pk1(t2), gt3 = pk1(t3);
            const float* wr = &sW2[kk * 4 * Dd + dbase];
#pragma unroll
            for (int q = 0; q < 6; q++) {
                ulonglong2 wa = *(const ulonglong2*)(wr + 4 * q);
                ulonglong2 wb = *(const ulonglong2*)(wr + Dd + 4 * q);
                ulonglong2 wc = *(const ulonglong2*)(wr + 2 * Dd + 4 * q);
                ulonglong2 wd = *(const ulonglong2*)(wr + 3 * Dd + 4 * q);
                h2o[2*q]   = ffma2(go0, wa.x, ffma2(go1, wb.x, ffma2(go2, wc.x, ffma2(go3, wd.x, h2o[2*q]))));
                h2o[2*q+1] = ffma2(go0, wa.y, ffma2(go1, wb.y, ffma2(go2, wc.y, ffma2(go3, wd.y, h2o[2*q+1]))));
                h2t[2*q]   = ffma2(gt0, wa.x, ffma2(gt1, wb.x, ffma2(gt2, wc.x, ffma2(gt3, wd.x, h2t[2*q]))));
                h2t[2*q+1] = ffma2(gt0, wa.y, ffma2(gt1, wb.y, ffma2(gt2, wc.y, ffma2(gt3, wd.y, h2t[2*q+1]))));
            }
            cv = cvn;
        }

        // ---- layer 3: o = gelu(h2) @ W3 + b3 ----
        u64 oo[12], ot[12];
#pragma unroll
        for (int q = 0; q < 12; q++) {
            u64 bb = *(const u64*)(sB3 + dbase + 2 * q);
            oo[q] = bb; ot[q] = bb;
        }
#pragma unroll
        for (int mq = 0; mq < 12; mq++) {
            float a0, a1, b0v, b1v;
            upk(h2o[mq], a0, a1);
            upk(h2t[mq], b0v, b1v);
            float gA0 = gelu_exact(a0),  gA1 = gelu_exact(a1);   // (m=dbase+2mq[,+1], j=jown)
            float gB0 = gelu_exact(b0v), gB1 = gelu_exact(b1v);  // (same m, j=joth)
            float gC0 = __shfl_xor_sync(0xFFFFFFFFu, gB0, 1);    // (m=obase+2mq,  j=jown)
            float gC1 = __shfl_xor_sync(0xFFFFFFFFu, gB1, 1);
            float gD0 = __shfl_xor_sync(0xFFFFFFFFu, gA0, 1);    // (m=obase+2mq,  j=joth)
            float gD1 = __shfl_xor_sync(0xFFFFFFFFu, gA1, 1);
            u64 pA0 = pk1(gA0), pA1 = pk1(gA1), pC0 = pk1(gC0), pC1 = pk1(gC1);
            u64 pB0 = pk1(gB0), pB1 = pk1(gB1), pD0 = pk1(gD0), pD1 = pk1(gD1);
            const float* ra = &sW3[(dbase + 2 * mq) * Dd + dbase];
            const float* rb = &sW3[(obase + 2 * mq) * Dd + dbase];
#pragma unroll
            for (int q = 0; q < 6; q++) {
                ulonglong2 wa0 = *(const ulonglong2*)(ra + 4 * q);
                ulonglong2 wa1 = *(const ulonglong2*)(ra + Dd + 4 * q);
                ulonglong2 wb0 = *(const ulonglong2*)(rb + 4 * q);
                ulonglong2 wb1 = *(const ulonglong2*)(rb + Dd + 4 * q);
                oo[2*q]   = ffma2(pA0, wa0.x, ffma2(pA1, wa1.x, ffma2(pC0, wb0.x, ffma2(pC1, wb1.x, oo[2*q]))));
                oo[2*q+1] = ffma2(pA0, wa0.y, ffma2(pA1, wa1.y, ffma2(pC0, wb0.y, ffma2(pC1, wb1.y, oo[2*q+1]))));
                ot[2*q]   = ffma2(pB0, wa0.x, ffma2(pB1, wa1.x, ffma2(pD0, wb0.x, ffma2(pD1, wb1.x, ot[2*q]))));
                ot[2*q+1] = ffma2(pB0, wa0.y, ffma2(pB1, wa1.y, ffma2(pD0, wb0.y, ffma2(pD1, wb1.y, ot[2*q+1]))));
            }
        }

        // ---- norms (half-sums exchanged across the lane pair) ----
        float n0 = 0.0f, n1 = 0.0f;
#pragma unroll
        for (int q = 0; q < 12; q++) {
            float x0, x1, y0, y1;
            upk(fmul2(oo[q], oo[q]), x0, x1); n0 += x0 + x1;
            upk(fmul2(ot[q], ot[q]), y0, y1); n1 += y0 + y1;
        }
        float r0 = __shfl_xor_sync(0xFFFFFFFFu, n1, 1);   // partner half of jown
        float r1 = __shfl_xor_sync(0xFFFFFFFFu, n0, 1);   // partner half of joth
        float wo = sqrtf(n0 + r0);
        float wt = sqrtf(n1 + r1);

        // ---- online softmax updates ----
        // jown: accumulate numerator AND denominator (each j is exactly one
        // lane's jown -> denominator counted once per j across the block).
        if (jown <= i) {
            float mn = fmaxf(mloc, wo);
            float rr = __expf(mloc - mn), ee = __expf(wo - mn);
            sloc = sloc * rr + ee;
            u64 rp = pk1(rr), ep = pk1(ee);
#pragma unroll
            for (int q = 0; q < 12; q++) accp[q] = ffma2(accp[q], rp, fmul2(oo[q], ep));
            mloc = mn;
        }
        // joth: accumulate numerator only (rescale sloc to stay consistent
        // with the updated mloc; do NOT add ee -> no double-counting).
        if (joth <= i) {
            float mn = fmaxf(mloc, wt);
            float rr = __expf(mloc - mn), ee = __expf(wt - mn);
            sloc = sloc * rr;
            u64 rp = pk1(rr), ep = pk1(ee);
#pragma unroll
            for (int q = 0; q < 12; q++) accp[q] = ffma2(accp[q], rp, fmul2(ot[q], ep));
            mloc = mn;
        }
    }

    // ---- block combine: max ----
    float M = mloc;
#pragma unroll
    for (int o = 16; o; o >>= 1) M = fmaxf(M, __shfl_xor_sync(0xFFFFFFFFu, M, o));
    if (lane == 0) sRed[wid] = M;
    __syncthreads();
    if (tid == 0) {
        float m = sRed[0];
#pragma unroll
        for (int w = 1; w < NW; w++) m = fmaxf(m, sRed[w]);
        sRed[8] = m;
    }
    __syncthreads();
    M = sRed[8];

    // ---- rescale + sum + accumulator reduce ----
    float sc = __expf(mloc - M);
    float ss = sloc * sc;
#pragma unroll
    for (int o = 16; o; o >>= 1) ss += __shfl_xor_sync(0xFFFFFFFFu, ss, o);
    if (lane == 0) sRed[wid] = ss;

    u64 scp = pk1(sc);
#pragma unroll
    for (int q = 0; q < 12; q++) {
        u64 v = fmul2(accp[q], scp);
#pragma unroll
        for (int o = 2; o <= 16; o <<= 1)
            v = fadd2(v, __shfl_xor_sync(0xFFFFFFFFu, v, o));
        accp[q] = v;   // lane0: sum over even lanes (d-half 0); lane1: odd lanes (half 1)
    }
    if (lane < 2) {
#pragma unroll
        for (int q = 0; q < 12; q++) {
            float x0, x1; upk(accp[q], x0, x1);
            sAcc[wid * Dd + dbase + 2 * q]     = x0;
            sAcc[wid * Dd + dbase + 2 * q + 1] = x1;
        }
    }
    __syncthreads();
    if (tid == 0) {
        float s = sRed[0];
#pragma unroll
        for (int w = 1; w < NW; w++) s += sRed[w];
        sRed[9] = 1.0f / s;
    }
    __syncthreads();
    if (tid < Dd) {
        float a = 0.0f;
#pragma unroll
        for (int w = 0; w < NW; w++) a += sAcc[w * Dd + tid];
        out[bi * Dd + tid] = a * sRed[9];
    }
}

// ---------------------------------------------------------------------------
extern "C" void kernel_launch(void* const* d_in, const int* in_sizes, int n_in,
                              void* d_out, int out_size) {
    const float* x  = (const float*)d_in[0];
    const float* W1 = (const float*)d_in[1];
    const float* b1 = (const float*)d_in[2];
    const float* W2 = (const float*)d_in[3];
    const float* b2 = (const float*)d_in[4];
    const float* W3 = (const float*)d_in[5];
    const float* b3 = (const float*)d_in[6];
    float* out = (float*)d_out;

    prep_kernel<<<BN, H1>>>(x, W1, b1);
    pair_kernel<<<BN, TPB>>>(W2, b2, W3, b3, out);
    (void)in_sizes; (void)n_in; (void)out_size;
}